// round 12
// baseline (speedup 1.0000x reference)
#include <cuda_runtime.h>
#include <cuda_bf16.h>

// Problem constants
#define LL 4096
#define HH 64
#define WW 64
#define DM 96
#define DI 192
#define DS 16
#define DTR 6
#define KK 4
#define CPROJ 38   // DT_RANK + 2*D_STATE
#define NSCAN (KK * DI)   // 768
#define NC 64             // chunks per scan
#define CL (LL / NC)      // 64 positions per chunk

// ---------------- scratch (device globals; no allocation allowed) ----------------
__device__ float  g_xz[LL * 2 * DI];          // [l][384]  (x_ | z)
__device__ float  g_xc[LL * DI];              // [l][192]  conv+silu output
__device__ float2 g_du[NSCAN * LL];           // [s][l] = (delta, delta*u)
__device__ float  g_uS[NSCAN * LL];           // [s][l] = u  (for D-term in pass2)
__device__ float2 g_bc[KK * LL * DS];         // [k][l][n] = (B, C)
__device__ float  g_bK[KK * LL * DS];         // [k][l][n] = B only (pass1)
__device__ float  g_outy[NSCAN * LL];         // [s][l]
__device__ float  g_yg[LL * DI];              // [l][d]  normalized*gated
__device__ float  g_carryA[NSCAN * NC * DS];  // chunk dA product
__device__ float  g_carryB[NSCAN * NC * DS];  // chunk local final h
__device__ float  g_hin[NSCAN * NC * DS];     // incoming state per chunk

__device__ __forceinline__ float ex2(float x) {
    float r;
    asm("ex2.approx.f32 %0, %1;" : "=f"(r) : "f"(x));
    return r;
}
#define LOG2E 1.4426950408889634f

// ---------------- generic tiled GEMM: C(MxN) = A(MxKc) * B(NxKc)^T ----------------
template<int BM, int BN, int BK, int TM, int TN>
__global__ void gemm_abt(const float* __restrict__ A, const float* __restrict__ B,
                         float* __restrict__ C, int M, int N, int Kc) {
    __shared__ float As[BK][BM + 1];
    __shared__ float Bs[BK][BN + 1];
    int tid = threadIdx.x;                    // 256 threads
    int block_row = blockIdx.y * BM;
    int block_col = blockIdx.x * BN;
    int tr = (tid / (BN / TN)) * TM;
    int tc = (tid % (BN / TN)) * TN;
    float acc[TM][TN];
#pragma unroll
    for (int i = 0; i < TM; i++)
#pragma unroll
        for (int j = 0; j < TN; j++) acc[i][j] = 0.f;

    for (int k0 = 0; k0 < Kc; k0 += BK) {
        for (int i = tid; i < BM * BK; i += 256) {
            int r = i / BK, c = i % BK;
            int gr = block_row + r, gc = k0 + c;
            As[c][r] = (gr < M && gc < Kc) ? A[gr * Kc + gc] : 0.f;
        }
        for (int i = tid; i < BN * BK; i += 256) {
            int r = i / BK, c = i % BK;
            int gr = block_col + r, gc = k0 + c;
            Bs[c][r] = (gr < N && gc < Kc) ? B[gr * Kc + gc] : 0.f;
        }
        __syncthreads();
#pragma unroll
        for (int kk = 0; kk < BK; kk++) {
            float a[TM], b[TN];
#pragma unroll
            for (int i = 0; i < TM; i++) a[i] = As[kk][tr + i];
#pragma unroll
            for (int j = 0; j < TN; j++) b[j] = Bs[kk][tc + j];
#pragma unroll
            for (int i = 0; i < TM; i++)
#pragma unroll
                for (int j = 0; j < TN; j++) acc[i][j] = fmaf(a[i], b[j], acc[i][j]);
        }
        __syncthreads();
    }
#pragma unroll
    for (int i = 0; i < TM; i++) {
        int gr = block_row + tr + i;
        if (gr >= M) continue;
#pragma unroll
        for (int j = 0; j < TN; j++) {
            int gc = block_col + tc + j;
            if (gc < N) C[gr * N + gc] = acc[i][j];
        }
    }
}

// ---------------- depthwise 3x3 conv (SAME) + bias + SiLU, 4 channels/thread ----------------
__global__ void conv_silu_kernel(const float* __restrict__ xz,
                                 const float* __restrict__ conv_w,
                                 const float* __restrict__ conv_b,
                                 float* __restrict__ xc) {
    int idx = blockIdx.x * 256 + threadIdx.x;          // over LL * DI/4
    if (idx >= LL * (DI / 4)) return;
    int d4 = idx % (DI / 4), l = idx / (DI / 4);
    int d0 = d4 * 4;
    int i = l / WW, j = l % WW;
    float4 s = *reinterpret_cast<const float4*>(conv_b + d0);
#pragma unroll
    for (int a = 0; a < 3; a++) {
        int ii = i + a - 1;
        if (ii < 0 || ii >= HH) continue;
#pragma unroll
        for (int bb = 0; bb < 3; bb++) {
            int jj = j + bb - 1;
            if (jj < 0 || jj >= WW) continue;
            float4 v = *reinterpret_cast<const float4*>(xz + (ii * WW + jj) * (2 * DI) + d0);
            float4 w = *reinterpret_cast<const float4*>(conv_w + (a * 3 + bb) * DI + d0);
            s.x = fmaf(v.x, w.x, s.x);
            s.y = fmaf(v.y, w.y, s.y);
            s.z = fmaf(v.z, w.z, s.z);
            s.w = fmaf(v.w, w.w, s.w);
        }
    }
    float4 o;
    o.x = s.x / (1.f + __expf(-s.x));
    o.y = s.y / (1.f + __expf(-s.y));
    o.z = s.z / (1.f + __expf(-s.z));
    o.w = s.w / (1.f + __expf(-s.w));
    *reinterpret_cast<float4*>(xc + l * DI + d0) = o;
}

// ---------------- x_dbl projection + delta (softplus) + pack scan inputs ----------------
__global__ void xdbl_kernel(const float* __restrict__ xc,
                            const float* __restrict__ x_proj_w,  // [K][38][192]
                            const float* __restrict__ dt_w,      // [K][192][6]
                            const float* __restrict__ dt_b,      // [K][192]
                            float2* __restrict__ du,             // [K*192][L] (delta, delta*u)
                            float* __restrict__ uS,              // [K*192][L] u
                            float2* __restrict__ bc,             // [K][L][16]
                            float* __restrict__ bK)              // [K][L][16] B only
{
    const int BL = 32;
    int k = blockIdx.y;
    int l0 = blockIdx.x * BL;
    int tid = threadIdx.x;
    __shared__ float u_s[BL][DI + 1];    // [li][c]  (stride 193: conflict-free scalar reads)
    __shared__ float xd_s[CPROJ][BL + 1];

    // load u tile: float4 LDG (c contiguous for every k), 4 scalar STS
    for (int e = tid; e < BL * (DI / 4); e += 256) {
        int li = e / (DI / 4), c4 = e % (DI / 4);
        int l = l0 + li;
        int lp = (k & 2) ? (LL - 1 - l) : l;                       // flip for k=2,3
        int sp = (k & 1) ? ((lp % WW) * WW + (lp / WW)) : lp;      // col-major for k=1,3
        float4 v = *reinterpret_cast<const float4*>(xc + sp * DI + c4 * 4);
        u_s[li][c4 * 4 + 0] = v.x;
        u_s[li][c4 * 4 + 1] = v.y;
        u_s[li][c4 * 4 + 2] = v.z;
        u_s[li][c4 * 4 + 3] = v.w;
    }
    __syncthreads();

    const float* Wk = x_proj_w + k * CPROJ * DI;
    for (int e = tid; e < CPROJ * BL; e += 256) {
        int row = e / BL, li = e % BL;
        const float4* w4 = reinterpret_cast<const float4*>(Wk + row * DI);  // 16B-aligned
        float s = 0.f;
#pragma unroll 8
        for (int c4 = 0; c4 < DI / 4; c4++) {
            float4 w = w4[c4];
            s = fmaf(w.x, u_s[li][c4 * 4 + 0], s);
            s = fmaf(w.y, u_s[li][c4 * 4 + 1], s);
            s = fmaf(w.z, u_s[li][c4 * 4 + 2], s);
            s = fmaf(w.w, u_s[li][c4 * 4 + 3], s);
        }
        xd_s[row][li] = s;
    }
    __syncthreads();

    for (int e = tid; e < DI * BL; e += 256) {
        int d = e / BL, li = e % BL;
        float acc = dt_b[k * DI + d];
        const float2* dw2 = reinterpret_cast<const float2*>(dt_w + (k * DI + d) * DTR); // 8B-aligned
#pragma unroll
        for (int r2 = 0; r2 < DTR / 2; r2++) {
            float2 w = dw2[r2];
            acc = fmaf(w.x, xd_s[r2 * 2 + 0][li], acc);
            acc = fmaf(w.y, xd_s[r2 * 2 + 1][li], acc);
        }
        float delta = (acc > 20.f) ? acc : log1pf(expf(acc));
        float u = u_s[li][d];
        size_t o = (size_t)(k * DI + d) * LL + l0 + li;
        du[o] = make_float2(delta, delta * u);
        uS[o] = u;
    }
    for (int e = tid; e < DS * BL; e += 256) {
        int li = e / DS, n = e % DS;
        float Bv = xd_s[DTR + n][li];
        size_t o = ((size_t)k * LL + l0 + li) * DS + n;
        bc[o] = make_float2(Bv, xd_s[DTR + DS + n][li]);
        bK[o] = Bv;
    }
}

// ---------------- scan pass 1: per-chunk transfer (P = prod dA, h = local final) ----------------
__global__ void scan_pass1(const float2* __restrict__ du,
                           const float* __restrict__ bK,
                           const float* __restrict__ A_logs,
                           float* __restrict__ carryA,
                           float* __restrict__ carryB)
{
    int hw = blockIdx.x * 8 + (threadIdx.x >> 4);   // 0 .. NSCAN*NC-1
    int n = threadIdx.x & 15;
    int c = hw / NSCAN;        // chunk index (block shares chunk, consecutive scans)
    int s = hw % NSCAN;
    int k = s / DI;
    float An2 = -__expf(A_logs[s * DS + n]) * LOG2E;
    const float2* dup = du + (size_t)s * LL + c * CL;
    const float* bp = bK + ((size_t)k * LL + c * CL) * DS;

    float P = 1.f, h = 0.f;
#pragma unroll 16
    for (int i = 0; i < CL; i++) {
        float2 dv = dup[i];                 // (delta, delta*u)
        float b  = bp[i * DS + n];
        float dA = ex2(dv.x * An2);
        P *= dA;
        h = fmaf(dA, h, dv.y * b);
    }
    carryA[((size_t)s * NC + c) * DS + n] = P;
    carryB[((size_t)s * NC + c) * DS + n] = h;
}

// ---------------- scan combine: fold chunk transfers sequentially (unrolled for MLP) ----------------
__global__ void scan_combine(const float* __restrict__ carryA,
                             const float* __restrict__ carryB,
                             float* __restrict__ hin)
{
    int s = blockIdx.x * 8 + (threadIdx.x >> 4);    // 0..767
    int n = threadIdx.x & 15;
    float h = 0.f;
    size_t base = (size_t)s * NC * DS + n;
#pragma unroll 8
    for (int c = 0; c < NC; c++) {
        hin[base + (size_t)c * DS] = h;
        h = fmaf(carryA[base + (size_t)c * DS], h, carryB[base + (size_t)c * DS]);
    }
}

// ---------------- scan pass 2: seeded recompute, smem-transpose y reduction ----------------
__global__ void scan_pass2(const float2* __restrict__ du,
                           const float* __restrict__ uS,
                           const float2* __restrict__ bc,
                           const float* __restrict__ A_logs,
                           const float* __restrict__ Ds,
                           const float* __restrict__ hin,
                           float* __restrict__ outy)
{
    int hwl = threadIdx.x >> 4;                     // 0..7
    int hw = blockIdx.x * 8 + hwl;
    int n = threadIdx.x & 15;
    int c = hw / NSCAN;
    int s = hw % NSCAN;
    int k = s / DI;
    float An2 = -__expf(A_logs[s * DS + n]) * LOG2E;
    float Dv = Ds[s];
    const float2* dup = du + (size_t)s * LL + c * CL;
    const float* up = uS + (size_t)s * LL + c * CL;
    const float2* bcp = bc + ((size_t)k * LL + c * CL) * DS;
    float* op = outy + (size_t)s * LL + c * CL;

    __shared__ float ysm[8][16][20];   // rows 80B: 16B-aligned for float4 reads
    float (*Y)[20] = ysm[hwl];

    float h = hin[((size_t)s * NC + c) * DS + n];
    for (int l0 = 0; l0 < CL; l0 += 16) {
#pragma unroll
        for (int i = 0; i < 16; i++) {
            float2 dv = dup[l0 + i];            // (delta, delta*u)
            float2 b  = bcp[(l0 + i) * DS + n];
            float dA = ex2(dv.x * An2);
            h = fmaf(dA, h, dv.y * b.x);
            Y[i][n] = h * b.y;
        }
        __syncwarp();
        float myu = up[l0 + n];                 // u at the position this lane writes
        float acc = Dv * myu;
        const float4* yr = reinterpret_cast<const float4*>(&Y[n][0]);
#pragma unroll
        for (int j = 0; j < 4; j++) {
            float4 v = yr[j];
            acc += v.x + v.y + v.z + v.w;
        }
        op[l0 + n] = acc;      // coalesced 64B per half-warp
        __syncwarp();
    }
}

// ---------------- sum over k + LayerNorm + SiLU(z) gate (coalesced, float4) ----------------
__global__ void ln_gate_kernel(const float* __restrict__ outy,
                               const float* __restrict__ xz,
                               const float* __restrict__ ln_g,
                               const float* __restrict__ ln_b,
                               float* __restrict__ yg) {
    const int TL = 32;
    int l0 = blockIdx.x * TL;
    int tid = threadIdx.x;   // 256
    __shared__ float ys[TL][DI + 1];

    // load + k-sum, float4 over l
    for (int e = tid; e < (TL / 4) * DI; e += 256) {
        int li4 = e & 7, d = e >> 3;
        int li0 = li4 * 4;
        float4 v = make_float4(0.f, 0.f, 0.f, 0.f);
#pragma unroll
        for (int k = 0; k < KK; k++) {
            float4 t = *reinterpret_cast<const float4*>(
                outy + ((size_t)(k * DI + d)) * LL + l0 + li0);
            v.x += t.x; v.y += t.y; v.z += t.z; v.w += t.w;
        }
        ys[li0 + 0][d] = v.x;
        ys[li0 + 1][d] = v.y;
        ys[li0 + 2][d] = v.z;
        ys[li0 + 3][d] = v.w;
    }
    __syncthreads();

    int w = tid >> 5, lane = tid & 31;
#pragma unroll
    for (int q = 0; q < 4; q++) {
        int li = w * 4 + q;
        int l = l0 + li;
        float v[6];
        float s1 = 0.f, s2 = 0.f;
#pragma unroll
        for (int j = 0; j < 6; j++) {
            v[j] = ys[li][lane + 32 * j];
            s1 += v[j];
            s2 += v[j] * v[j];
        }
#pragma unroll
        for (int off = 16; off; off >>= 1) {
            s1 += __shfl_xor_sync(0xffffffffu, s1, off);
            s2 += __shfl_xor_sync(0xffffffffu, s2, off);
        }
        float mu = s1 * (1.f / DI);
        float var = s2 * (1.f / DI) - mu * mu;
        float inv = rsqrtf(var + 1e-5f);
#pragma unroll
        for (int j = 0; j < 6; j++) {
            int d = lane + 32 * j;
            float yn = fmaf((v[j] - mu) * inv, ln_g[d], ln_b[d]);
            float z = xz[l * (2 * DI) + DI + d];
            yg[l * DI + d] = yn * (z / (1.f + __expf(-z)));
        }
    }
}

// ---------------- launch ----------------
extern "C" void kernel_launch(void* const* d_in, const int* in_sizes, int n_in,
                              void* d_out, int out_size) {
    const float* x        = (const float*)d_in[0];
    const float* in_proj  = (const float*)d_in[1];
    const float* conv_w   = (const float*)d_in[2];
    const float* conv_b   = (const float*)d_in[3];
    const float* x_proj_w = (const float*)d_in[4];
    const float* dt_w     = (const float*)d_in[5];
    const float* dt_b     = (const float*)d_in[6];
    const float* A_logs   = (const float*)d_in[7];
    const float* Ds       = (const float*)d_in[8];
    const float* ln_g     = (const float*)d_in[9];
    const float* ln_b     = (const float*)d_in[10];
    const float* out_w    = (const float*)d_in[11];
    float* out = (float*)d_out;

    float*  xz  = nullptr; cudaGetSymbolAddress((void**)&xz,  g_xz);
    float*  xc  = nullptr; cudaGetSymbolAddress((void**)&xc,  g_xc);
    float2* du  = nullptr; cudaGetSymbolAddress((void**)&du,  g_du);
    float*  uS  = nullptr; cudaGetSymbolAddress((void**)&uS,  g_uS);
    float2* bcp = nullptr; cudaGetSymbolAddress((void**)&bcp, g_bc);
    float*  bK  = nullptr; cudaGetSymbolAddress((void**)&bK,  g_bK);
    float*  oy  = nullptr; cudaGetSymbolAddress((void**)&oy,  g_outy);
    float*  yg  = nullptr; cudaGetSymbolAddress((void**)&yg,  g_yg);
    float*  cA  = nullptr; cudaGetSymbolAddress((void**)&cA,  g_carryA);
    float*  cB  = nullptr; cudaGetSymbolAddress((void**)&cB,  g_carryB);
    float*  hin = nullptr; cudaGetSymbolAddress((void**)&hin, g_hin);

    // 1) in_proj: xz(4096x384) = x(4096x96) @ in_proj_w(384x96)^T
    gemm_abt<64, 64, 16, 4, 4><<<dim3(6, 64), 256>>>(x, in_proj, xz, LL, 2 * DI, DM);
    // 2) depthwise conv + SiLU
    conv_silu_kernel<<<(LL * (DI / 4) + 255) / 256, 256>>>(xz, conv_w, conv_b, xc);
    // 3) x_dbl projection + delta + pack scan inputs
    xdbl_kernel<<<dim3(LL / 32, KK), 256>>>(xc, x_proj_w, dt_w, dt_b, du, uS, bcp, bK);
    // 4) chunked selective scan
    scan_pass1<<<NSCAN * NC / 8, 128>>>(du, bK, A_logs, cA, cB);
    scan_combine<<<NSCAN / 8, 128>>>(cA, cB, hin);
    scan_pass2<<<NSCAN * NC / 8, 128>>>(du, uS, bcp, A_logs, Ds, hin, oy);
    // 5) sum over k + LN + gate
    ln_gate_kernel<<<LL / 32, 256>>>(oy, xz, ln_g, ln_b, yg);
    // 6) out_proj: out(4096x96) = yg(4096x192) @ out_w(96x192)^T
    gemm_abt<64, 64, 16, 4, 4><<<dim3(2, 64), 256>>>(yg, out_w, out, LL, DM, DI);
}

// round 14
// speedup vs baseline: 1.0435x; 1.0435x over previous
#include <cuda_runtime.h>
#include <cuda_bf16.h>

// Problem constants
#define LL 4096
#define HH 64
#define WW 64
#define DM 96
#define DI 192
#define DS 16
#define DTR 6
#define KK 4
#define CPROJ 38   // DT_RANK + 2*D_STATE
#define NSCAN (KK * DI)   // 768
#define NC 64             // chunks per scan
#define CL (LL / NC)      // 64 positions per chunk

// ---------------- scratch (device globals; no allocation allowed) ----------------
__device__ float  g_xz[LL * 2 * DI];          // [l][384]  (x_ | z)
__device__ float  g_xc[LL * DI];              // [l][192]  conv+silu output
__device__ float2 g_du[NSCAN * LL];           // [s][l] = (delta, u)
__device__ float2 g_bc[KK * LL * DS];         // [k][l][n] = (B, C)
__device__ float  g_bK[KK * LL * DS];         // [k][l][n] = B only (pass1)
__device__ float  g_outy[NSCAN * LL];         // [s][l]
__device__ float  g_yg[LL * DI];              // [l][d]  normalized*gated
__device__ float  g_carryA[NSCAN * NC * DS];  // chunk dA product
__device__ float  g_carryB[NSCAN * NC * DS];  // chunk local final h
__device__ float  g_hin[NSCAN * NC * DS];     // incoming state per chunk

__device__ __forceinline__ float ex2(float x) {
    float r;
    asm("ex2.approx.f32 %0, %1;" : "=f"(r) : "f"(x));
    return r;
}
#define LOG2E 1.4426950408889634f

// ---------------- generic tiled GEMM: C(MxN) = A(MxKc) * B(NxKc)^T ----------------
template<int BM, int BN, int BK, int TM, int TN>
__global__ void gemm_abt(const float* __restrict__ A, const float* __restrict__ B,
                         float* __restrict__ C, int M, int N, int Kc) {
    __shared__ float As[BK][BM + 1];
    __shared__ float Bs[BK][BN + 1];
    int tid = threadIdx.x;                    // 256 threads
    int block_row = blockIdx.y * BM;
    int block_col = blockIdx.x * BN;
    int tr = (tid / (BN / TN)) * TM;
    int tc = (tid % (BN / TN)) * TN;
    float acc[TM][TN];
#pragma unroll
    for (int i = 0; i < TM; i++)
#pragma unroll
        for (int j = 0; j < TN; j++) acc[i][j] = 0.f;

    for (int k0 = 0; k0 < Kc; k0 += BK) {
        for (int i = tid; i < BM * BK; i += 256) {
            int r = i / BK, c = i % BK;
            int gr = block_row + r, gc = k0 + c;
            As[c][r] = (gr < M && gc < Kc) ? A[gr * Kc + gc] : 0.f;
        }
        for (int i = tid; i < BN * BK; i += 256) {
            int r = i / BK, c = i % BK;
            int gr = block_col + r, gc = k0 + c;
            Bs[c][r] = (gr < N && gc < Kc) ? B[gr * Kc + gc] : 0.f;
        }
        __syncthreads();
#pragma unroll
        for (int kk = 0; kk < BK; kk++) {
            float a[TM], b[TN];
#pragma unroll
            for (int i = 0; i < TM; i++) a[i] = As[kk][tr + i];
#pragma unroll
            for (int j = 0; j < TN; j++) b[j] = Bs[kk][tc + j];
#pragma unroll
            for (int i = 0; i < TM; i++)
#pragma unroll
                for (int j = 0; j < TN; j++) acc[i][j] = fmaf(a[i], b[j], acc[i][j]);
        }
        __syncthreads();
    }
#pragma unroll
    for (int i = 0; i < TM; i++) {
        int gr = block_row + tr + i;
        if (gr >= M) continue;
#pragma unroll
        for (int j = 0; j < TN; j++) {
            int gc = block_col + tc + j;
            if (gc < N) C[gr * N + gc] = acc[i][j];
        }
    }
}

// ---------------- depthwise 3x3 conv (SAME) + bias + SiLU, 4 channels/thread ----------------
__global__ void conv_silu_kernel(const float* __restrict__ xz,
                                 const float* __restrict__ conv_w,
                                 const float* __restrict__ conv_b,
                                 float* __restrict__ xc) {
    int idx = blockIdx.x * 256 + threadIdx.x;          // over LL * DI/4
    if (idx >= LL * (DI / 4)) return;
    int d4 = idx % (DI / 4), l = idx / (DI / 4);
    int d0 = d4 * 4;
    int i = l / WW, j = l % WW;
    float4 s = *reinterpret_cast<const float4*>(conv_b + d0);
#pragma unroll
    for (int a = 0; a < 3; a++) {
        int ii = i + a - 1;
        if (ii < 0 || ii >= HH) continue;
#pragma unroll
        for (int bb = 0; bb < 3; bb++) {
            int jj = j + bb - 1;
            if (jj < 0 || jj >= WW) continue;
            float4 v = *reinterpret_cast<const float4*>(xz + (ii * WW + jj) * (2 * DI) + d0);
            float4 w = *reinterpret_cast<const float4*>(conv_w + (a * 3 + bb) * DI + d0);
            s.x = fmaf(v.x, w.x, s.x);
            s.y = fmaf(v.y, w.y, s.y);
            s.z = fmaf(v.z, w.z, s.z);
            s.w = fmaf(v.w, w.w, s.w);
        }
    }
    float4 o;
    o.x = s.x / (1.f + __expf(-s.x));
    o.y = s.y / (1.f + __expf(-s.y));
    o.z = s.z / (1.f + __expf(-s.z));
    o.w = s.w / (1.f + __expf(-s.w));
    *reinterpret_cast<float4*>(xc + l * DI + d0) = o;
}

// ---------------- x_dbl projection + delta (softplus) + pack scan inputs ----------------
__global__ void xdbl_kernel(const float* __restrict__ xc,
                            const float* __restrict__ x_proj_w,  // [K][38][192]
                            const float* __restrict__ dt_w,      // [K][192][6]
                            const float* __restrict__ dt_b,      // [K][192]
                            float2* __restrict__ du,             // [K*192][L] (delta, u)
                            float2* __restrict__ bc,             // [K][L][16]
                            float* __restrict__ bK)              // [K][L][16] B only
{
    const int BL = 32;
    int k = blockIdx.y;
    int l0 = blockIdx.x * BL;
    int tid = threadIdx.x;
    __shared__ float u_s[BL][DI + 1];    // [li][c]  (stride 193: conflict-free scalar reads)
    __shared__ float xd_s[CPROJ][BL + 1];

    // load u tile: float4 LDG (c contiguous for every k), 4 scalar STS
    for (int e = tid; e < BL * (DI / 4); e += 256) {
        int li = e / (DI / 4), c4 = e % (DI / 4);
        int l = l0 + li;
        int lp = (k & 2) ? (LL - 1 - l) : l;                       // flip for k=2,3
        int sp = (k & 1) ? ((lp % WW) * WW + (lp / WW)) : lp;      // col-major for k=1,3
        float4 v = *reinterpret_cast<const float4*>(xc + sp * DI + c4 * 4);
        u_s[li][c4 * 4 + 0] = v.x;
        u_s[li][c4 * 4 + 1] = v.y;
        u_s[li][c4 * 4 + 2] = v.z;
        u_s[li][c4 * 4 + 3] = v.w;
    }
    __syncthreads();

    const float* Wk = x_proj_w + k * CPROJ * DI;
    for (int e = tid; e < CPROJ * BL; e += 256) {
        int row = e / BL, li = e % BL;
        const float4* w4 = reinterpret_cast<const float4*>(Wk + row * DI);  // 16B-aligned
        float s = 0.f;
#pragma unroll 8
        for (int c4 = 0; c4 < DI / 4; c4++) {
            float4 w = w4[c4];
            s = fmaf(w.x, u_s[li][c4 * 4 + 0], s);
            s = fmaf(w.y, u_s[li][c4 * 4 + 1], s);
            s = fmaf(w.z, u_s[li][c4 * 4 + 2], s);
            s = fmaf(w.w, u_s[li][c4 * 4 + 3], s);
        }
        xd_s[row][li] = s;
    }
    __syncthreads();

    for (int e = tid; e < DI * BL; e += 256) {
        int d = e / BL, li = e % BL;
        float acc = dt_b[k * DI + d];
        const float2* dw2 = reinterpret_cast<const float2*>(dt_w + (k * DI + d) * DTR); // 8B-aligned
#pragma unroll
        for (int r2 = 0; r2 < DTR / 2; r2++) {
            float2 w = dw2[r2];
            acc = fmaf(w.x, xd_s[r2 * 2 + 0][li], acc);
            acc = fmaf(w.y, xd_s[r2 * 2 + 1][li], acc);
        }
        float delta = (acc > 20.f) ? acc : log1pf(expf(acc));
        du[(k * DI + d) * LL + l0 + li] = make_float2(delta, u_s[li][d]);
    }
    for (int e = tid; e < DS * BL; e += 256) {
        int li = e / DS, n = e % DS;
        float Bv = xd_s[DTR + n][li];
        size_t o = ((size_t)k * LL + l0 + li) * DS + n;
        bc[o] = make_float2(Bv, xd_s[DTR + DS + n][li]);
        bK[o] = Bv;
    }
}

// ---------------- scan pass 1: per-chunk transfer (P = prod dA, h = local final) ----------------
__global__ void scan_pass1(const float2* __restrict__ du,
                           const float* __restrict__ bK,
                           const float* __restrict__ A_logs,
                           float* __restrict__ carryA,
                           float* __restrict__ carryB)
{
    int hw = blockIdx.x * 8 + (threadIdx.x >> 4);   // 0 .. NSCAN*NC-1
    int n = threadIdx.x & 15;
    int c = hw / NSCAN;        // chunk index (block shares chunk, consecutive scans)
    int s = hw % NSCAN;
    int k = s / DI;
    float An2 = -__expf(A_logs[s * DS + n]) * LOG2E;
    const float2* dup = du + (size_t)s * LL + c * CL;
    const float* bp = bK + ((size_t)k * LL + c * CL) * DS;

    float P = 1.f, h = 0.f;
#pragma unroll 16
    for (int i = 0; i < CL; i++) {
        float2 dv = dup[i];                 // (delta, u)
        float b  = bp[i * DS + n];
        float dA = ex2(dv.x * An2);
        P *= dA;
        h = fmaf(dA, h, dv.x * dv.y * b);
    }
    carryA[((size_t)s * NC + c) * DS + n] = P;
    carryB[((size_t)s * NC + c) * DS + n] = h;
}

// ---------------- scan combine: fold chunk transfers sequentially (unrolled for MLP) ----------------
__global__ void scan_combine(const float* __restrict__ carryA,
                             const float* __restrict__ carryB,
                             float* __restrict__ hin)
{
    int s = blockIdx.x * 8 + (threadIdx.x >> 4);    // 0..767
    int n = threadIdx.x & 15;
    float h = 0.f;
    size_t base = (size_t)s * NC * DS + n;
#pragma unroll 8
    for (int c = 0; c < NC; c++) {
        hin[base + (size_t)c * DS] = h;
        h = fmaf(carryA[base + (size_t)c * DS], h, carryB[base + (size_t)c * DS]);
    }
}

// ---------------- scan pass 2: seeded recompute, smem-transpose y reduction ----------------
__global__ void scan_pass2(const float2* __restrict__ du,
                           const float2* __restrict__ bc,
                           const float* __restrict__ A_logs,
                           const float* __restrict__ Ds,
                           const float* __restrict__ hin,
                           float* __restrict__ outy)
{
    int hwl = threadIdx.x >> 4;                     // 0..7
    int hw = blockIdx.x * 8 + hwl;
    int n = threadIdx.x & 15;
    int c = hw / NSCAN;
    int s = hw % NSCAN;
    int k = s / DI;
    float An2 = -__expf(A_logs[s * DS + n]) * LOG2E;
    float Dv = Ds[s];
    const float2* dup = du + (size_t)s * LL + c * CL;
    const float2* bcp = bc + ((size_t)k * LL + c * CL) * DS;
    float* op = outy + (size_t)s * LL + c * CL;

    __shared__ float ysm[8][16][20];   // rows 80B: 16B-aligned for float4 reads
    float (*Y)[20] = ysm[hwl];

    float h = hin[((size_t)s * NC + c) * DS + n];
    for (int l0 = 0; l0 < CL; l0 += 16) {
#pragma unroll
        for (int i = 0; i < 16; i++) {
            float2 dv = dup[l0 + i];            // (delta, u)
            float2 b  = bcp[(l0 + i) * DS + n];
            float dA = ex2(dv.x * An2);
            h = fmaf(dA, h, dv.x * dv.y * b.x);
            Y[i][n] = h * b.y;
        }
        __syncwarp();
        float myu = dup[l0 + n].y;              // u at the position this lane writes
        float acc = Dv * myu;
        const float4* yr = reinterpret_cast<const float4*>(&Y[n][0]);
#pragma unroll
        for (int j = 0; j < 4; j++) {
            float4 v = yr[j];
            acc += v.x + v.y + v.z + v.w;
        }
        op[l0 + n] = acc;      // coalesced 64B per half-warp
        __syncwarp();
    }
}

// ---------------- sum over k + LayerNorm + SiLU(z) gate (coalesced, float4) ----------------
__global__ void ln_gate_kernel(const float* __restrict__ outy,
                               const float* __restrict__ xz,
                               const float* __restrict__ ln_g,
                               const float* __restrict__ ln_b,
                               float* __restrict__ yg) {
    const int TL = 32;
    int l0 = blockIdx.x * TL;
    int tid = threadIdx.x;   // 256
    __shared__ float ys[TL][DI + 1];

    // load + k-sum, float4 over l
    for (int e = tid; e < (TL / 4) * DI; e += 256) {
        int li4 = e & 7, d = e >> 3;
        int li0 = li4 * 4;
        float4 v = make_float4(0.f, 0.f, 0.f, 0.f);
#pragma unroll
        for (int k = 0; k < KK; k++) {
            float4 t = *reinterpret_cast<const float4*>(
                outy + ((size_t)(k * DI + d)) * LL + l0 + li0);
            v.x += t.x; v.y += t.y; v.z += t.z; v.w += t.w;
        }
        ys[li0 + 0][d] = v.x;
        ys[li0 + 1][d] = v.y;
        ys[li0 + 2][d] = v.z;
        ys[li0 + 3][d] = v.w;
    }
    __syncthreads();

    int w = tid >> 5, lane = tid & 31;
#pragma unroll
    for (int q = 0; q < 4; q++) {
        int li = w * 4 + q;
        int l = l0 + li;
        float v[6];
        float s1 = 0.f, s2 = 0.f;
#pragma unroll
        for (int j = 0; j < 6; j++) {
            v[j] = ys[li][lane + 32 * j];
            s1 += v[j];
            s2 += v[j] * v[j];
        }
#pragma unroll
        for (int off = 16; off; off >>= 1) {
            s1 += __shfl_xor_sync(0xffffffffu, s1, off);
            s2 += __shfl_xor_sync(0xffffffffu, s2, off);
        }
        float mu = s1 * (1.f / DI);
        float var = s2 * (1.f / DI) - mu * mu;
        float inv = rsqrtf(var + 1e-5f);
#pragma unroll
        for (int j = 0; j < 6; j++) {
            int d = lane + 32 * j;
            float yn = fmaf((v[j] - mu) * inv, ln_g[d], ln_b[d]);
            float z = xz[l * (2 * DI) + DI + d];
            yg[l * DI + d] = yn * (z / (1.f + __expf(-z)));
        }
    }
}

// ---------------- launch ----------------
extern "C" void kernel_launch(void* const* d_in, const int* in_sizes, int n_in,
                              void* d_out, int out_size) {
    const float* x        = (const float*)d_in[0];
    const float* in_proj  = (const float*)d_in[1];
    const float* conv_w   = (const float*)d_in[2];
    const float* conv_b   = (const float*)d_in[3];
    const float* x_proj_w = (const float*)d_in[4];
    const float* dt_w     = (const float*)d_in[5];
    const float* dt_b     = (const float*)d_in[6];
    const float* A_logs   = (const float*)d_in[7];
    const float* Ds       = (const float*)d_in[8];
    const float* ln_g     = (const float*)d_in[9];
    const float* ln_b     = (const float*)d_in[10];
    const float* out_w    = (const float*)d_in[11];
    float* out = (float*)d_out;

    float*  xz  = nullptr; cudaGetSymbolAddress((void**)&xz,  g_xz);
    float*  xc  = nullptr; cudaGetSymbolAddress((void**)&xc,  g_xc);
    float2* du  = nullptr; cudaGetSymbolAddress((void**)&du,  g_du);
    float2* bcp = nullptr; cudaGetSymbolAddress((void**)&bcp, g_bc);
    float*  bK  = nullptr; cudaGetSymbolAddress((void**)&bK,  g_bK);
    float*  oy  = nullptr; cudaGetSymbolAddress((void**)&oy,  g_outy);
    float*  yg  = nullptr; cudaGetSymbolAddress((void**)&yg,  g_yg);
    float*  cA  = nullptr; cudaGetSymbolAddress((void**)&cA,  g_carryA);
    float*  cB  = nullptr; cudaGetSymbolAddress((void**)&cB,  g_carryB);
    float*  hin = nullptr; cudaGetSymbolAddress((void**)&hin, g_hin);

    // 1) in_proj: xz(4096x384) = x(4096x96) @ in_proj_w(384x96)^T
    gemm_abt<64, 64, 16, 4, 4><<<dim3(6, 64), 256>>>(x, in_proj, xz, LL, 2 * DI, DM);
    // 2) depthwise conv + SiLU
    conv_silu_kernel<<<(LL * (DI / 4) + 255) / 256, 256>>>(xz, conv_w, conv_b, xc);
    // 3) x_dbl projection + delta + pack scan inputs
    xdbl_kernel<<<dim3(LL / 32, KK), 256>>>(xc, x_proj_w, dt_w, dt_b, du, bcp, bK);
    // 4) chunked selective scan
    scan_pass1<<<NSCAN * NC / 8, 128>>>(du, bK, A_logs, cA, cB);
    scan_combine<<<NSCAN / 8, 128>>>(cA, cB, hin);
    scan_pass2<<<NSCAN * NC / 8, 128>>>(du, bcp, A_logs, Ds, hin, oy);
    // 5) sum over k + LN + gate
    ln_gate_kernel<<<LL / 32, 256>>>(oy, xz, ln_g, ln_b, yg);
    // 6) out_proj: out(4096x96) = yg(4096x192) @ out_w(96x192)^T
    gemm_abt<64, 64, 16, 4, 4><<<dim3(2, 64), 256>>>(yg, out_w, out, LL, DM, DI);
}

// round 15
// speedup vs baseline: 1.0862x; 1.0410x over previous
#include <cuda_runtime.h>
#include <cuda_bf16.h>

// Problem constants
#define LL 4096
#define HH 64
#define WW 64
#define DM 96
#define DI 192
#define DS 16
#define DTR 6
#define KK 4
#define CPROJ 38   // DT_RANK + 2*D_STATE
#define NSCAN (KK * DI)   // 768
#define NC 64             // chunks per scan
#define CL (LL / NC)      // 64 positions per chunk

// ---------------- scratch (device globals; no allocation allowed) ----------------
__device__ float  g_xz[LL * 2 * DI];          // [l][384]  (x_ | z)
__device__ float  g_xc[LL * DI];              // [l][192]  conv+silu output
__device__ float2 g_du[NSCAN * LL];           // [s][l] = (delta, u)
__device__ float2 g_bc[KK * LL * DS];         // [k][l][n] = (B, C)
__device__ float  g_bK[KK * LL * DS];         // [k][l][n] = B only (pass1)
__device__ float  g_outy[NSCAN * LL];         // [s][l]
__device__ float  g_yg[LL * DI];              // [l][d]  normalized*gated
__device__ float  g_carryA[NSCAN * NC * DS];  // chunk dA product
__device__ float  g_carryB[NSCAN * NC * DS];  // chunk local final h
__device__ float  g_hin[NSCAN * NC * DS];     // incoming state per chunk

__device__ __forceinline__ float ex2(float x) {
    float r;
    asm("ex2.approx.f32 %0, %1;" : "=f"(r) : "f"(x));
    return r;
}
#define LOG2E 1.4426950408889634f

// ---------------- generic tiled GEMM: C(MxN) = A(MxKc) * B(NxKc)^T ----------------
template<int BM, int BN, int BK, int TM, int TN>
__global__ void gemm_abt(const float* __restrict__ A, const float* __restrict__ B,
                         float* __restrict__ C, int M, int N, int Kc) {
    __shared__ float As[BK][BM + 1];
    __shared__ float Bs[BK][BN + 1];
    int tid = threadIdx.x;                    // 256 threads
    int block_row = blockIdx.y * BM;
    int block_col = blockIdx.x * BN;
    int tr = (tid / (BN / TN)) * TM;
    int tc = (tid % (BN / TN)) * TN;
    float acc[TM][TN];
#pragma unroll
    for (int i = 0; i < TM; i++)
#pragma unroll
        for (int j = 0; j < TN; j++) acc[i][j] = 0.f;

    for (int k0 = 0; k0 < Kc; k0 += BK) {
        for (int i = tid; i < BM * BK; i += 256) {
            int r = i / BK, c = i % BK;
            int gr = block_row + r, gc = k0 + c;
            As[c][r] = (gr < M && gc < Kc) ? A[gr * Kc + gc] : 0.f;
        }
        for (int i = tid; i < BN * BK; i += 256) {
            int r = i / BK, c = i % BK;
            int gr = block_col + r, gc = k0 + c;
            Bs[c][r] = (gr < N && gc < Kc) ? B[gr * Kc + gc] : 0.f;
        }
        __syncthreads();
#pragma unroll
        for (int kk = 0; kk < BK; kk++) {
            float a[TM], b[TN];
#pragma unroll
            for (int i = 0; i < TM; i++) a[i] = As[kk][tr + i];
#pragma unroll
            for (int j = 0; j < TN; j++) b[j] = Bs[kk][tc + j];
#pragma unroll
            for (int i = 0; i < TM; i++)
#pragma unroll
                for (int j = 0; j < TN; j++) acc[i][j] = fmaf(a[i], b[j], acc[i][j]);
        }
        __syncthreads();
    }
#pragma unroll
    for (int i = 0; i < TM; i++) {
        int gr = block_row + tr + i;
        if (gr >= M) continue;
#pragma unroll
        for (int j = 0; j < TN; j++) {
            int gc = block_col + tc + j;
            if (gc < N) C[gr * N + gc] = acc[i][j];
        }
    }
}

// ---------------- depthwise 3x3 conv (SAME) + bias + SiLU, 4 channels/thread ----------------
__global__ void conv_silu_kernel(const float* __restrict__ xz,
                                 const float* __restrict__ conv_w,
                                 const float* __restrict__ conv_b,
                                 float* __restrict__ xc) {
    int idx = blockIdx.x * 256 + threadIdx.x;          // over LL * DI/4
    if (idx >= LL * (DI / 4)) return;
    int d4 = idx % (DI / 4), l = idx / (DI / 4);
    int d0 = d4 * 4;
    int i = l / WW, j = l % WW;
    float4 s = *reinterpret_cast<const float4*>(conv_b + d0);
#pragma unroll
    for (int a = 0; a < 3; a++) {
        int ii = i + a - 1;
        if (ii < 0 || ii >= HH) continue;
#pragma unroll
        for (int bb = 0; bb < 3; bb++) {
            int jj = j + bb - 1;
            if (jj < 0 || jj >= WW) continue;
            float4 v = *reinterpret_cast<const float4*>(xz + (ii * WW + jj) * (2 * DI) + d0);
            float4 w = *reinterpret_cast<const float4*>(conv_w + (a * 3 + bb) * DI + d0);
            s.x = fmaf(v.x, w.x, s.x);
            s.y = fmaf(v.y, w.y, s.y);
            s.z = fmaf(v.z, w.z, s.z);
            s.w = fmaf(v.w, w.w, s.w);
        }
    }
    float4 o;
    o.x = s.x / (1.f + __expf(-s.x));
    o.y = s.y / (1.f + __expf(-s.y));
    o.z = s.z / (1.f + __expf(-s.z));
    o.w = s.w / (1.f + __expf(-s.w));
    *reinterpret_cast<float4*>(xc + l * DI + d0) = o;
}

// ---------------- x_dbl projection + delta (softplus) + pack scan inputs ----------------
__global__ void xdbl_kernel(const float* __restrict__ xc,
                            const float* __restrict__ x_proj_w,  // [K][38][192]
                            const float* __restrict__ dt_w,      // [K][192][6]
                            const float* __restrict__ dt_b,      // [K][192]
                            float2* __restrict__ du,             // [K*192][L] (delta, u)
                            float2* __restrict__ bc,             // [K][L][16]
                            float* __restrict__ bK)              // [K][L][16] B only
{
    const int BL = 32;
    int k = blockIdx.y;
    int l0 = blockIdx.x * BL;
    int tid = threadIdx.x;
    __shared__ float u_s[BL][DI + 1];    // [li][c]  (stride 193: conflict-free scalar reads)
    __shared__ float xd_s[CPROJ][BL + 1];

    // load u tile: float4 LDG (c contiguous for every k), 4 scalar STS
    for (int e = tid; e < BL * (DI / 4); e += 256) {
        int li = e / (DI / 4), c4 = e % (DI / 4);
        int l = l0 + li;
        int lp = (k & 2) ? (LL - 1 - l) : l;                       // flip for k=2,3
        int sp = (k & 1) ? ((lp % WW) * WW + (lp / WW)) : lp;      // col-major for k=1,3
        float4 v = *reinterpret_cast<const float4*>(xc + sp * DI + c4 * 4);
        u_s[li][c4 * 4 + 0] = v.x;
        u_s[li][c4 * 4 + 1] = v.y;
        u_s[li][c4 * 4 + 2] = v.z;
        u_s[li][c4 * 4 + 3] = v.w;
    }
    __syncthreads();

    const float* Wk = x_proj_w + k * CPROJ * DI;
    for (int e = tid; e < CPROJ * BL; e += 256) {
        int row = e / BL, li = e % BL;
        const float4* w4 = reinterpret_cast<const float4*>(Wk + row * DI);  // 16B-aligned
        float s = 0.f;
#pragma unroll 8
        for (int c4 = 0; c4 < DI / 4; c4++) {
            float4 w = w4[c4];
            s = fmaf(w.x, u_s[li][c4 * 4 + 0], s);
            s = fmaf(w.y, u_s[li][c4 * 4 + 1], s);
            s = fmaf(w.z, u_s[li][c4 * 4 + 2], s);
            s = fmaf(w.w, u_s[li][c4 * 4 + 3], s);
        }
        xd_s[row][li] = s;
    }
    __syncthreads();

    for (int e = tid; e < DI * BL; e += 256) {
        int d = e / BL, li = e % BL;
        float acc = dt_b[k * DI + d];
        const float2* dw2 = reinterpret_cast<const float2*>(dt_w + (k * DI + d) * DTR); // 8B-aligned
#pragma unroll
        for (int r2 = 0; r2 < DTR / 2; r2++) {
            float2 w = dw2[r2];
            acc = fmaf(w.x, xd_s[r2 * 2 + 0][li], acc);
            acc = fmaf(w.y, xd_s[r2 * 2 + 1][li], acc);
        }
        float delta = (acc > 20.f) ? acc : log1pf(expf(acc));
        du[(k * DI + d) * LL + l0 + li] = make_float2(delta, u_s[li][d]);
    }
    for (int e = tid; e < DS * BL; e += 256) {
        int li = e / DS, n = e % DS;
        float Bv = xd_s[DTR + n][li];
        size_t o = ((size_t)k * LL + l0 + li) * DS + n;
        bc[o] = make_float2(Bv, xd_s[DTR + DS + n][li]);
        bK[o] = Bv;
    }
}

// ---------------- scan pass 1: per-chunk transfer (P = prod dA, h = local final) ----------------
__global__ void scan_pass1(const float2* __restrict__ du,
                           const float* __restrict__ bK,
                           const float* __restrict__ A_logs,
                           float* __restrict__ carryA,
                           float* __restrict__ carryB)
{
    int hw = blockIdx.x * 8 + (threadIdx.x >> 4);   // 0 .. NSCAN*NC-1
    int n = threadIdx.x & 15;
    int c = hw / NSCAN;        // chunk index (block shares chunk, consecutive scans)
    int s = hw % NSCAN;
    int k = s / DI;
    float An2 = -__expf(A_logs[s * DS + n]) * LOG2E;
    const float2* dup = du + (size_t)s * LL + c * CL;
    const float* bp = bK + ((size_t)k * LL + c * CL) * DS;

    float P = 1.f, h = 0.f;
#pragma unroll 16
    for (int i = 0; i < CL; i++) {
        float2 dv = dup[i];                 // (delta, u)
        float b  = bp[i * DS + n];
        float dA = ex2(dv.x * An2);
        P *= dA;
        h = fmaf(dA, h, dv.x * dv.y * b);
    }
    carryA[((size_t)s * NC + c) * DS + n] = P;
    carryB[((size_t)s * NC + c) * DS + n] = h;
}

// ---------------- scan combine: fold chunk transfers sequentially (unrolled for MLP) ----------------
__global__ void scan_combine(const float* __restrict__ carryA,
                             const float* __restrict__ carryB,
                             float* __restrict__ hin)
{
    int s = blockIdx.x * 8 + (threadIdx.x >> 4);    // 0..767
    int n = threadIdx.x & 15;
    float h = 0.f;
    size_t base = (size_t)s * NC * DS + n;
#pragma unroll 8
    for (int c = 0; c < NC; c++) {
        hin[base + (size_t)c * DS] = h;
        h = fmaf(carryA[base + (size_t)c * DS], h, carryB[base + (size_t)c * DS]);
    }
}

// ---------------- scan pass 2: seeded recompute, smem-transpose y reduction ----------------
__global__ void scan_pass2(const float2* __restrict__ du,
                           const float2* __restrict__ bc,
                           const float* __restrict__ A_logs,
                           const float* __restrict__ Ds,
                           const float* __restrict__ hin,
                           float* __restrict__ outy)
{
    int hwl = threadIdx.x >> 4;                     // 0..7
    int hw = blockIdx.x * 8 + hwl;
    int n = threadIdx.x & 15;
    int c = hw / NSCAN;
    int s = hw % NSCAN;
    int k = s / DI;
    float An2 = -__expf(A_logs[s * DS + n]) * LOG2E;
    float Dv = Ds[s];
    const float2* dup = du + (size_t)s * LL + c * CL;
    const float2* bcp = bc + ((size_t)k * LL + c * CL) * DS;
    float* op = outy + (size_t)s * LL + c * CL;

    __shared__ float ysm[8][16][17];   // stride 17: conflict-free both directions
    float (*Y)[17] = ysm[hwl];

    float h = hin[((size_t)s * NC + c) * DS + n];
    for (int l0 = 0; l0 < CL; l0 += 16) {
#pragma unroll
        for (int i = 0; i < 16; i++) {
            float2 dv = dup[l0 + i];            // (delta, u)
            float2 b  = bcp[(l0 + i) * DS + n];
            float dA = ex2(dv.x * An2);
            h = fmaf(dA, h, dv.x * dv.y * b.x);
            Y[i][n] = h * b.y;
        }
        __syncwarp();
        float myu = dup[l0 + n].y;              // u at the position this lane writes
        float acc = Dv * myu;
#pragma unroll
        for (int j = 0; j < 16; j++) acc += Y[n][j];
        op[l0 + n] = acc;      // coalesced 64B per half-warp
        __syncwarp();
    }
}

// ---------------- sum over k + LayerNorm + SiLU(z) gate (coalesced, float4) ----------------
__global__ void ln_gate_kernel(const float* __restrict__ outy,
                               const float* __restrict__ xz,
                               const float* __restrict__ ln_g,
                               const float* __restrict__ ln_b,
                               float* __restrict__ yg) {
    const int TL = 32;
    int l0 = blockIdx.x * TL;
    int tid = threadIdx.x;   // 256
    __shared__ float ys[TL][DI + 1];

    // load + k-sum, float4 over l
    for (int e = tid; e < (TL / 4) * DI; e += 256) {
        int li4 = e & 7, d = e >> 3;
        int li0 = li4 * 4;
        float4 v = make_float4(0.f, 0.f, 0.f, 0.f);
#pragma unroll
        for (int k = 0; k < KK; k++) {
            float4 t = *reinterpret_cast<const float4*>(
                outy + ((size_t)(k * DI + d)) * LL + l0 + li0);
            v.x += t.x; v.y += t.y; v.z += t.z; v.w += t.w;
        }
        ys[li0 + 0][d] = v.x;
        ys[li0 + 1][d] = v.y;
        ys[li0 + 2][d] = v.z;
        ys[li0 + 3][d] = v.w;
    }
    __syncthreads();

    int w = tid >> 5, lane = tid & 31;
#pragma unroll
    for (int q = 0; q < 4; q++) {
        int li = w * 4 + q;
        int l = l0 + li;
        float v[6];
        float s1 = 0.f, s2 = 0.f;
#pragma unroll
        for (int j = 0; j < 6; j++) {
            v[j] = ys[li][lane + 32 * j];
            s1 += v[j];
            s2 += v[j] * v[j];
        }
#pragma unroll
        for (int off = 16; off; off >>= 1) {
            s1 += __shfl_xor_sync(0xffffffffu, s1, off);
            s2 += __shfl_xor_sync(0xffffffffu, s2, off);
        }
        float mu = s1 * (1.f / DI);
        float var = s2 * (1.f / DI) - mu * mu;
        float inv = rsqrtf(var + 1e-5f);
#pragma unroll
        for (int j = 0; j < 6; j++) {
            int d = lane + 32 * j;
            float yn = fmaf((v[j] - mu) * inv, ln_g[d], ln_b[d]);
            float z = xz[l * (2 * DI) + DI + d];
            yg[l * DI + d] = yn * (z / (1.f + __expf(-z)));
        }
    }
}

// ---------------- launch ----------------
extern "C" void kernel_launch(void* const* d_in, const int* in_sizes, int n_in,
                              void* d_out, int out_size) {
    const float* x        = (const float*)d_in[0];
    const float* in_proj  = (const float*)d_in[1];
    const float* conv_w   = (const float*)d_in[2];
    const float* conv_b   = (const float*)d_in[3];
    const float* x_proj_w = (const float*)d_in[4];
    const float* dt_w     = (const float*)d_in[5];
    const float* dt_b     = (const float*)d_in[6];
    const float* A_logs   = (const float*)d_in[7];
    const float* Ds       = (const float*)d_in[8];
    const float* ln_g     = (const float*)d_in[9];
    const float* ln_b     = (const float*)d_in[10];
    const float* out_w    = (const float*)d_in[11];
    float* out = (float*)d_out;

    float*  xz  = nullptr; cudaGetSymbolAddress((void**)&xz,  g_xz);
    float*  xc  = nullptr; cudaGetSymbolAddress((void**)&xc,  g_xc);
    float2* du  = nullptr; cudaGetSymbolAddress((void**)&du,  g_du);
    float2* bcp = nullptr; cudaGetSymbolAddress((void**)&bcp, g_bc);
    float*  bK  = nullptr; cudaGetSymbolAddress((void**)&bK,  g_bK);
    float*  oy  = nullptr; cudaGetSymbolAddress((void**)&oy,  g_outy);
    float*  yg  = nullptr; cudaGetSymbolAddress((void**)&yg,  g_yg);
    float*  cA  = nullptr; cudaGetSymbolAddress((void**)&cA,  g_carryA);
    float*  cB  = nullptr; cudaGetSymbolAddress((void**)&cB,  g_carryB);
    float*  hin = nullptr; cudaGetSymbolAddress((void**)&hin, g_hin);

    // 1) in_proj: xz(4096x384) = x(4096x96) @ in_proj_w(384x96)^T
    gemm_abt<64, 64, 16, 4, 4><<<dim3(6, 64), 256>>>(x, in_proj, xz, LL, 2 * DI, DM);
    // 2) depthwise conv + SiLU
    conv_silu_kernel<<<(LL * (DI / 4) + 255) / 256, 256>>>(xz, conv_w, conv_b, xc);
    // 3) x_dbl projection + delta + pack scan inputs
    xdbl_kernel<<<dim3(LL / 32, KK), 256>>>(xc, x_proj_w, dt_w, dt_b, du, bcp, bK);
    // 4) chunked selective scan
    scan_pass1<<<NSCAN * NC / 8, 128>>>(du, bK, A_logs, cA, cB);
    scan_combine<<<NSCAN / 8, 128>>>(cA, cB, hin);
    scan_pass2<<<NSCAN * NC / 8, 128>>>(du, bcp, A_logs, Ds, hin, oy);
    // 5) sum over k + LN + gate
    ln_gate_kernel<<<LL / 32, 256>>>(oy, xz, ln_g, ln_b, yg);
    // 6) out_proj: out(4096x96) = yg(4096x192) @ out_w(96x192)^T
    gemm_abt<64, 64, 16, 4, 4><<<dim3(2, 64), 256>>>(yg, out_w, out, LL, DM, DI);
}